// round 1
// baseline (speedup 1.0000x reference)
#include <cuda_runtime.h>
#include <math.h>

#define NN 50000
#define FF 128
#define CC 512
#define EE 800000
#define HH 256

// Output layout: new_x [C,F], new_adj [C,C], new_batch [C], S [N,C]
#define OFF_ADJ   (CC*FF)               // 65536
#define OFF_BATCH (OFF_ADJ + CC*CC)     // 327680
#define OFF_S     (OFF_BATCH + CC)      // 328192

// ---------------- scratch (static device globals; no allocation) -----------
__device__ __align__(16) float g_h[(size_t)NN * CC];   // GEMM output
__device__ __align__(16) float g_z[(size_t)NN * CC];   // post-agg activations
__device__ float g_inv[NN];
__device__ int   g_deg[NN];
__device__ int   g_off[NN + 1];
__device__ int   g_cur[NN];
__device__ int   g_csr_src[EE];
__device__ float g_csr_cf[EE];
__device__ int   g_cluster[NN];
__device__ float g_hs[NN];
__device__ int   g_sdeg[NN];
__device__ float g_invs[NN];
__device__ float g_sagg[NN];
__device__ float g_score[NN];
__device__ int   g_icnt[CC];
__device__ int   g_segkey[CC];
__device__ int   g_segidx[CC];

// monotone float<->int key (order-preserving) for atomicMax on floats
__device__ __forceinline__ int fkey(float f) {
    int b = __float_as_int(f);
    return b < 0 ? (b ^ 0x7FFFFFFF) : b;
}
__device__ __forceinline__ float fdec(int k) {
    return __int_as_float(k < 0 ? (k ^ 0x7FFFFFFF) : k);
}

// ---------------- init / degree / csr --------------------------------------
__global__ void k_init(float* out) {
    int i = blockIdx.x * blockDim.x + threadIdx.x;
    int stride = gridDim.x * blockDim.x;
    for (int j = i; j < NN; j += stride) { g_deg[j] = 0; g_sdeg[j] = 0; g_sagg[j] = 0.f; }
    for (int j = i; j < CC; j += stride) {
        g_icnt[j] = 0; g_segkey[j] = (int)0x80000000; g_segidx[j] = NN;
        out[OFF_BATCH + j] = 0.f;
    }
    for (int j = i; j < CC * CC; j += stride) out[OFF_ADJ + j] = 0.f;
}

__global__ void k_deg(const int* __restrict__ ei) {
    int e = blockIdx.x * blockDim.x + threadIdx.x;
    if (e < EE) atomicAdd(&g_deg[ei[EE + e]], 1);
}

__global__ void k_inv() {
    int i = blockIdx.x * blockDim.x + threadIdx.x;
    if (i < NN) g_inv[i] = rsqrtf((float)g_deg[i] + 1.0f);
}

__global__ void __launch_bounds__(512) k_scan() {
    __shared__ int ssum[512];
    int t = threadIdx.x;
    const int chunk = (NN + 511) / 512;
    int b = t * chunk, e = min(b + chunk, NN);
    int s = 0;
    for (int i = b; i < e; i++) s += g_deg[i];
    ssum[t] = s;
    __syncthreads();
    for (int off = 1; off < 512; off <<= 1) {
        int v = (t >= off) ? ssum[t - off] : 0;
        __syncthreads();
        ssum[t] += v;
        __syncthreads();
    }
    int run = (t > 0) ? ssum[t - 1] : 0;
    for (int i = b; i < e; i++) { g_off[i] = run; g_cur[i] = run; run += g_deg[i]; }
    if (t == 0) g_off[NN] = ssum[511];
}

__global__ void k_fill(const int* __restrict__ ei) {
    int e = blockIdx.x * blockDim.x + threadIdx.x;
    if (e >= EE) return;
    int s = ei[e], d = ei[EE + e];
    int p = atomicAdd(&g_cur[d], 1);
    g_csr_src[p] = s;
    g_csr_cf[p] = g_inv[s] * g_inv[d];
}

// ---------------- SGEMM: C[M,Nc] = A[M,K] @ B[K,Nc] ------------------------
// BM=128 BN=64 BK=16, 256 threads, thread tile 8x4
__global__ void __launch_bounds__(256) k_gemm(const float* __restrict__ A,
                                              const float* __restrict__ B,
                                              float* __restrict__ Cm,
                                              int M, int K, int Nc) {
    __shared__ float As[16][132];
    __shared__ float Bs[16][64];
    const int tid = threadIdx.x;
    const int tx = tid & 15;   // N dir
    const int ty = tid >> 4;   // M dir
    const int rowBase = blockIdx.y * 128;
    const int colBase = blockIdx.x * 64;

    float acc[8][4];
#pragma unroll
    for (int m = 0; m < 8; m++)
#pragma unroll
        for (int n = 0; n < 4; n++) acc[m][n] = 0.f;

    for (int k0 = 0; k0 < K; k0 += 16) {
#pragma unroll
        for (int s = 0; s < 2; s++) {
            int lin = tid + s * 256;        // 0..511
            int r = lin >> 2;               // 0..127
            int c4 = (lin & 3) << 2;        // 0,4,8,12
            float4 v = make_float4(0.f, 0.f, 0.f, 0.f);
            int gr = rowBase + r;
            if (gr < M) v = *(const float4*)(A + (size_t)gr * K + k0 + c4);
            As[c4 + 0][r] = v.x; As[c4 + 1][r] = v.y;
            As[c4 + 2][r] = v.z; As[c4 + 3][r] = v.w;
        }
        {
            int r = tid >> 4;
            int c4 = (tid & 15) << 2;
            float4 v = *(const float4*)(B + (size_t)(k0 + r) * Nc + colBase + c4);
            *(float4*)&Bs[r][c4] = v;
        }
        __syncthreads();
#pragma unroll
        for (int k = 0; k < 16; k++) {
            float a[8];
#pragma unroll
            for (int m = 0; m < 8; m++) a[m] = As[k][ty * 8 + m];
            float4 bv = *(const float4*)&Bs[k][tx * 4];
            float bb[4] = {bv.x, bv.y, bv.z, bv.w};
#pragma unroll
            for (int m = 0; m < 8; m++)
#pragma unroll
                for (int n = 0; n < 4; n++) acc[m][n] = fmaf(a[m], bb[n], acc[m][n]);
        }
        __syncthreads();
    }
#pragma unroll
    for (int m = 0; m < 8; m++) {
        int gr = rowBase + ty * 8 + m;
        if (gr < M) {
            float4 v = make_float4(acc[m][0], acc[m][1], acc[m][2], acc[m][3]);
            *(float4*)(Cm + (size_t)gr * Nc + colBase + tx * 4) = v;
        }
    }
}

// ---------------- aggregation (CSR, block per node) -------------------------
template <int D>
__global__ void __launch_bounds__(256) k_agg(const float* __restrict__ h,
                                             float* __restrict__ z,
                                             const float* __restrict__ bias) {
    constexpr int FP = D / 256;
    int i = blockIdx.x;
    int beg = g_off[i], end = g_off[i + 1];
    float inv = g_inv[i];
    float self = inv * inv;
    float acc[FP];
#pragma unroll
    for (int q = 0; q < FP; q++)
        acc[q] = self * h[(size_t)i * D + threadIdx.x + q * 256];

    __shared__ int   s_src[128];
    __shared__ float s_cf[128];
    for (int e0 = beg; e0 < end; e0 += 128) {
        int m = min(128, end - e0);
        __syncthreads();
        if (threadIdx.x < m) {
            s_src[threadIdx.x] = g_csr_src[e0 + threadIdx.x];
            s_cf[threadIdx.x]  = g_csr_cf[e0 + threadIdx.x];
        }
        __syncthreads();
        for (int j = 0; j < m; j++) {
            const float* hr = h + (size_t)s_src[j] * D + threadIdx.x;
            float c = s_cf[j];
#pragma unroll
            for (int q = 0; q < FP; q++) acc[q] = fmaf(c, hr[q * 256], acc[q]);
        }
    }
#pragma unroll
    for (int q = 0; q < FP; q++) {
        float v = acc[q] + bias[threadIdx.x + q * 256];
        z[(size_t)i * D + threadIdx.x + q * 256] = fmaxf(v, 0.f);
    }
}

// ---------------- softmax + argmax (first-max tie rule) ---------------------
__global__ void __launch_bounds__(256) k_softmax(const float* __restrict__ logits,
                                                 float* __restrict__ S) {
    int i = blockIdx.x;
    int t = threadIdx.x;
    const float* row = logits + (size_t)i * CC;
    float v0 = row[t], v1 = row[t + 256];
    float bv = v0; int bi = t;
    if (v1 > bv) { bv = v1; bi = t + 256; }

    __shared__ float sv[256];
    __shared__ int   si[256];
    sv[t] = bv; si[t] = bi;
    __syncthreads();
    for (int s = 128; s > 0; s >>= 1) {
        if (t < s) {
            float ov = sv[t + s]; int oi = si[t + s];
            if (ov > sv[t] || (ov == sv[t] && oi < si[t])) { sv[t] = ov; si[t] = oi; }
        }
        __syncthreads();
    }
    float m = sv[0];
    if (t == 0) g_cluster[i] = si[0];
    __syncthreads();

    float e0 = expf(v0 - m), e1 = expf(v1 - m);
    sv[t] = e0 + e1;
    __syncthreads();
    for (int s = 128; s > 0; s >>= 1) {
        if (t < s) sv[t] += sv[t + s];
        __syncthreads();
    }
    float invsum = 1.0f / sv[0];
    S[(size_t)i * CC + t]       = e0 * invsum;
    S[(size_t)i * CC + t + 256] = e1 * invsum;
}

// ---------------- score layer (scalar GCN on intra-cluster subgraph) --------
__global__ void k_hs(const float* __restrict__ x, const float* __restrict__ Ws) {
    int g = blockIdx.x * blockDim.x + threadIdx.x;
    int w = g >> 5, lane = g & 31;
    if (w >= NN) return;
    float s = 0.f;
    for (int f = lane; f < FF; f += 32) s = fmaf(x[(size_t)w * FF + f], Ws[f], s);
#pragma unroll
    for (int off = 16; off > 0; off >>= 1) s += __shfl_down_sync(0xFFFFFFFF, s, off);
    if (lane == 0) g_hs[w] = s;
}

__global__ void k_intradeg(const int* __restrict__ ei) {
    int e = blockIdx.x * blockDim.x + threadIdx.x;
    if (e >= EE) return;
    int s = ei[e], d = ei[EE + e];
    int cs = g_cluster[s], cd = g_cluster[d];
    if (cs == cd) {
        atomicAdd(&g_sdeg[d], 1);
        atomicAdd(&g_icnt[cs], 1);
    }
}

__global__ void k_invs() {
    int i = blockIdx.x * blockDim.x + threadIdx.x;
    if (i < NN) g_invs[i] = rsqrtf((float)g_sdeg[i] + 1.0f);
}

__global__ void k_sagg(const int* __restrict__ ei) {
    int e = blockIdx.x * blockDim.x + threadIdx.x;
    if (e >= EE) return;
    int s = ei[e], d = ei[EE + e];
    if (g_cluster[s] == g_cluster[d])
        atomicAdd(&g_sagg[d], g_invs[s] * g_invs[d] * g_hs[s]);
}

__global__ void k_score(const float* __restrict__ bs) {
    int i = blockIdx.x * blockDim.x + threadIdx.x;
    if (i >= NN) return;
    float inv = g_invs[i];
    float v = g_sagg[i] + inv * inv * g_hs[i] + bs[0];
    g_score[i] = tanhf(v);
}

__global__ void k_segmax() {
    int i = blockIdx.x * blockDim.x + threadIdx.x;
    if (i >= NN) return;
    atomicMax(&g_segkey[g_cluster[i]], fkey(g_score[i]));
}

__global__ void k_segidx() {
    int i = blockIdx.x * blockDim.x + threadIdx.x;
    if (i >= NN) return;
    int c = g_cluster[i];
    float mx = fdec(g_segkey[c]);
    if (g_score[i] >= mx) atomicMin(&g_segidx[c], i);
}

// ---------------- pooling + adjacency ---------------------------------------
__global__ void __launch_bounds__(128) k_pool(const float* __restrict__ x,
                                              float* __restrict__ out) {
    int c = blockIdx.x;
    bool ne = g_icnt[c] > 0;
    float alpha = ne ? fdec(g_segkey[c]) : 0.f;
    int idx = min(g_segidx[c], NN - 1);
    out[(size_t)c * FF + threadIdx.x] = x[(size_t)idx * FF + threadIdx.x] * alpha;
}

__global__ void k_adj(const int* __restrict__ ei, float* __restrict__ out) {
    int e = blockIdx.x * blockDim.x + threadIdx.x;
    if (e >= EE) return;
    int cs = g_cluster[ei[e]], cd = g_cluster[ei[EE + e]];
    if (cs != cd && g_icnt[cs] > 0 && g_icnt[cd] > 0)
        out[OFF_ADJ + (size_t)cs * CC + cd] = 1.0f;
}

// ---------------- launch ----------------------------------------------------
extern "C" void kernel_launch(void* const* d_in, const int* in_sizes, int n_in,
                              void* d_out, int out_size) {
    const float* x   = (const float*)d_in[0];
    const int*   ei  = (const int*)d_in[1];
    // d_in[2] = batch (all zeros, unused)
    const float* W1  = (const float*)d_in[3];
    const float* b1  = (const float*)d_in[4];
    const float* W2  = (const float*)d_in[5];
    const float* b2  = (const float*)d_in[6];
    const float* W3  = (const float*)d_in[7];
    const float* b3  = (const float*)d_in[8];
    const float* Ws  = (const float*)d_in[9];
    const float* bs  = (const float*)d_in[10];
    float* out = (float*)d_out;

    const int EB = (EE + 255) / 256;
    const int NB = (NN + 255) / 256;

    k_init<<<512, 256>>>(out);
    k_deg<<<EB, 256>>>(ei);
    k_inv<<<NB, 256>>>();
    k_scan<<<1, 512>>>();
    k_fill<<<EB, 256>>>(ei);

    // layer 1: h = x @ W1 ; agg -> z1
    {
        dim3 g(HH / 64, (NN + 127) / 128);
        k_gemm<<<g, 256>>>(x, W1, g_h, NN, FF, HH);
        k_agg<256><<<NN, 256>>>(g_h, g_z, b1);
    }
    // layer 2
    {
        dim3 g(HH / 64, (NN + 127) / 128);
        k_gemm<<<g, 256>>>(g_z, W2, g_h, NN, HH, HH);
        k_agg<256><<<NN, 256>>>(g_h, g_z, b2);
    }
    // layer 3
    {
        dim3 g(CC / 64, (NN + 127) / 128);
        k_gemm<<<g, 256>>>(g_z, W3, g_h, NN, HH, CC);
        k_agg<512><<<NN, 256>>>(g_h, g_z, b3);
    }

    k_softmax<<<NN, 256>>>(g_z, out + OFF_S);

    k_hs<<<(NN * 32 + 255) / 256, 256>>>(x, Ws);
    k_intradeg<<<EB, 256>>>(ei);
    k_invs<<<NB, 256>>>();
    k_sagg<<<EB, 256>>>(ei);
    k_score<<<NB, 256>>>(bs);
    k_segmax<<<NB, 256>>>();
    k_segidx<<<NB, 256>>>();
    k_pool<<<CC, 128>>>(x, out);
    k_adj<<<EB, 256>>>(ei, out);

    (void)in_sizes; (void)n_in; (void)out_size;
}

// round 2
// speedup vs baseline: 1.4898x; 1.4898x over previous
#include <cuda_runtime.h>
#include <math.h>

#define NN 50000
#define FF 128
#define CC 512
#define EE 800000
#define HH 256

// Output layout: new_x [C,F], new_adj [C,C], new_batch [C], S [N,C]
#define OFF_ADJ   (CC*FF)
#define OFF_BATCH (OFF_ADJ + CC*CC)
#define OFF_S     (OFF_BATCH + CC)

// ---------------- scratch ----------------------------------------------------
__device__ __align__(16) float g_h[(size_t)NN * CC];   // buffer A (up to 512 wide)
__device__ __align__(16) float g_z[(size_t)NN * HH];   // buffer B (up to 256 wide)
__device__ float g_inv[NN];
__device__ int   g_deg[NN];
__device__ int   g_off[NN + 1];
__device__ int   g_cur[NN];
__device__ int   g_csr_src[EE];
__device__ float g_csr_cf[EE];
__device__ int   g_cluster[NN];
__device__ float g_hs[NN];
__device__ int   g_sdeg[NN];
__device__ float g_invs[NN];
__device__ float g_sagg[NN];
__device__ float g_score[NN];
__device__ int   g_icnt[CC];
__device__ int   g_segkey[CC];
__device__ int   g_segidx[CC];
__device__ int   g_bsum[256];
__device__ int   g_bpref[256];

__device__ __forceinline__ int fkey(float f) {
    int b = __float_as_int(f);
    return b < 0 ? (b ^ 0x7FFFFFFF) : b;
}
__device__ __forceinline__ float fdec(int k) {
    return __int_as_float(k < 0 ? (k ^ 0x7FFFFFFF) : k);
}

// ---------------- init / degree / csr ----------------------------------------
__global__ void k_init(float* out) {
    int i = blockIdx.x * blockDim.x + threadIdx.x;
    int stride = gridDim.x * blockDim.x;
    for (int j = i; j < NN; j += stride) { g_deg[j] = 0; g_sdeg[j] = 0; g_sagg[j] = 0.f; }
    for (int j = i; j < CC; j += stride) {
        g_icnt[j] = 0; g_segkey[j] = (int)0x80000000; g_segidx[j] = NN;
        out[OFF_BATCH + j] = 0.f;
    }
    for (int j = i; j < CC * CC; j += stride) out[OFF_ADJ + j] = 0.f;
}

__global__ void k_deg(const int* __restrict__ ei) {
    int e = blockIdx.x * blockDim.x + threadIdx.x;
    if (e < EE) atomicAdd(&g_deg[ei[EE + e]], 1);
}

__global__ void k_inv() {
    int i = blockIdx.x * blockDim.x + threadIdx.x;
    if (i < NN) g_inv[i] = rsqrtf((float)g_deg[i] + 1.0f);
}

// grid scan over g_deg -> g_off (exclusive), 3 phases
__global__ void __launch_bounds__(256) k_scan1() {
    __shared__ int s[256];
    int t = threadIdx.x;
    int i = blockIdx.x * 256 + t;
    int v = (i < NN) ? g_deg[i] : 0;
    s[t] = v;
    __syncthreads();
    for (int off = 1; off < 256; off <<= 1) {
        int u = (t >= off) ? s[t - off] : 0;
        __syncthreads();
        s[t] += u;
        __syncthreads();
    }
    if (i < NN) g_off[i] = s[t] - v;          // exclusive within block
    if (t == 255) g_bsum[blockIdx.x] = s[255];
}
__global__ void __launch_bounds__(256) k_scan2(int nblocks) {
    __shared__ int s[256];
    int t = threadIdx.x;
    int v = (t < nblocks) ? g_bsum[t] : 0;
    s[t] = v;
    __syncthreads();
    for (int off = 1; off < 256; off <<= 1) {
        int u = (t >= off) ? s[t - off] : 0;
        __syncthreads();
        s[t] += u;
        __syncthreads();
    }
    g_bpref[t] = s[t] - v;
    if (t == 255) g_off[NN] = s[255];
}
__global__ void __launch_bounds__(256) k_scan3() {
    int i = blockIdx.x * 256 + threadIdx.x;
    if (i < NN) {
        int o = g_off[i] + g_bpref[blockIdx.x];
        g_off[i] = o;
        g_cur[i] = o;
    }
}

__global__ void k_fill(const int* __restrict__ ei) {
    int e = blockIdx.x * blockDim.x + threadIdx.x;
    if (e >= EE) return;
    int s = ei[e], d = ei[EE + e];
    int p = atomicAdd(&g_cur[d], 1);
    g_csr_src[p] = s;
    g_csr_cf[p] = g_inv[s] * g_inv[d];
}

// ---------------- aggregation BEFORE gemm (linear reassociation) -------------
// z[i,:] = inv(i)^2 * h[i,:] + sum_{e:dst=i} cf(e) * h[src(e),:]
template <int D>
__global__ void __launch_bounds__(D) k_agg(const float* __restrict__ h,
                                           float* __restrict__ z) {
    int i = blockIdx.x;
    int t = threadIdx.x;
    int beg = g_off[i], end = g_off[i + 1];
    float inv = g_inv[i];
    float acc = inv * inv * __ldg(h + (size_t)i * D + t);

    int j = beg;
    for (; j + 4 <= end; j += 4) {
        int s0 = __ldg(g_csr_src + j + 0);
        int s1 = __ldg(g_csr_src + j + 1);
        int s2 = __ldg(g_csr_src + j + 2);
        int s3 = __ldg(g_csr_src + j + 3);
        float c0 = __ldg(g_csr_cf + j + 0);
        float c1 = __ldg(g_csr_cf + j + 1);
        float c2 = __ldg(g_csr_cf + j + 2);
        float c3 = __ldg(g_csr_cf + j + 3);
        float v0 = __ldg(h + (size_t)s0 * D + t);
        float v1 = __ldg(h + (size_t)s1 * D + t);
        float v2 = __ldg(h + (size_t)s2 * D + t);
        float v3 = __ldg(h + (size_t)s3 * D + t);
        acc = fmaf(c0, v0, acc);
        acc = fmaf(c1, v1, acc);
        acc = fmaf(c2, v2, acc);
        acc = fmaf(c3, v3, acc);
    }
    for (; j < end; j++) {
        int s0 = __ldg(g_csr_src + j);
        float c0 = __ldg(g_csr_cf + j);
        acc = fmaf(c0, __ldg(h + (size_t)s0 * D + t), acc);
    }
    z[(size_t)i * D + t] = acc;
}

// ---------------- SGEMM 128x128x8, 256 thr, 8x8 micro, fused bias+ReLU -------
__global__ void __launch_bounds__(256) k_gemm(const float* __restrict__ A,
                                              const float* __restrict__ B,
                                              const float* __restrict__ bias,
                                              float* __restrict__ Cm,
                                              int M, int K, int Nc) {
    __shared__ float As[8][128];
    __shared__ float Bs[8][128];
    const int tid = threadIdx.x;
    const int tx = tid & 15;         // N dir  (8 cols each)
    const int ty = tid >> 4;         // M dir  (8 rows each)
    const int rowBase = blockIdx.y * 128;
    const int colBase = blockIdx.x * 128;

    // A tile loader mapping: each thread 1 float4: row r=tid>>1, col4=(tid&1)*4
    const int ar = tid >> 1;
    const int ac4 = (tid & 1) * 4;
    // B tile loader: row r=tid>>5 (0..7), col4=(tid&31)*4
    const int br = tid >> 5;
    const int bc4 = (tid & 31) * 4;

    float acc[8][8];
#pragma unroll
    for (int m = 0; m < 8; m++)
#pragma unroll
        for (int n = 0; n < 8; n++) acc[m][n] = 0.f;

    for (int k0 = 0; k0 < K; k0 += 8) {
        {
            float4 v = make_float4(0.f, 0.f, 0.f, 0.f);
            int gr = rowBase + ar;
            if (gr < M) v = *(const float4*)(A + (size_t)gr * K + k0 + ac4);
            As[ac4 + 0][ar] = v.x;
            As[ac4 + 1][ar] = v.y;
            As[ac4 + 2][ar] = v.z;
            As[ac4 + 3][ar] = v.w;
        }
        {
            float4 v = *(const float4*)(B + (size_t)(k0 + br) * Nc + colBase + bc4);
            *(float4*)&Bs[br][bc4] = v;
        }
        __syncthreads();
#pragma unroll
        for (int k = 0; k < 8; k++) {
            float4 a0 = *(const float4*)&As[k][ty * 8];
            float4 a1 = *(const float4*)&As[k][ty * 8 + 4];
            float4 b0 = *(const float4*)&Bs[k][tx * 8];
            float4 b1 = *(const float4*)&Bs[k][tx * 8 + 4];
            float a[8] = {a0.x, a0.y, a0.z, a0.w, a1.x, a1.y, a1.z, a1.w};
            float b[8] = {b0.x, b0.y, b0.z, b0.w, b1.x, b1.y, b1.z, b1.w};
#pragma unroll
            for (int m = 0; m < 8; m++)
#pragma unroll
                for (int n = 0; n < 8; n++) acc[m][n] = fmaf(a[m], b[n], acc[m][n]);
        }
        __syncthreads();
    }

    float4 bb0 = *(const float4*)(bias + colBase + tx * 8);
    float4 bb1 = *(const float4*)(bias + colBase + tx * 8 + 4);
    float bc[8] = {bb0.x, bb0.y, bb0.z, bb0.w, bb1.x, bb1.y, bb1.z, bb1.w};

#pragma unroll
    for (int m = 0; m < 8; m++) {
        int gr = rowBase + ty * 8 + m;
        if (gr < M) {
            float4 v0 = make_float4(fmaxf(acc[m][0] + bc[0], 0.f),
                                    fmaxf(acc[m][1] + bc[1], 0.f),
                                    fmaxf(acc[m][2] + bc[2], 0.f),
                                    fmaxf(acc[m][3] + bc[3], 0.f));
            float4 v1 = make_float4(fmaxf(acc[m][4] + bc[4], 0.f),
                                    fmaxf(acc[m][5] + bc[5], 0.f),
                                    fmaxf(acc[m][6] + bc[6], 0.f),
                                    fmaxf(acc[m][7] + bc[7], 0.f));
            *(float4*)(Cm + (size_t)gr * Nc + colBase + tx * 8) = v0;
            *(float4*)(Cm + (size_t)gr * Nc + colBase + tx * 8 + 4) = v1;
        }
    }
}

// ---------------- softmax + argmax (first-max tie rule) ----------------------
__global__ void __launch_bounds__(256) k_softmax(const float* __restrict__ logits,
                                                 float* __restrict__ S) {
    int i = blockIdx.x;
    int t = threadIdx.x;
    const float* row = logits + (size_t)i * CC;
    float v0 = row[t], v1 = row[t + 256];
    float bv = v0; int bi = t;
    if (v1 > bv) { bv = v1; bi = t + 256; }

    __shared__ float sv[256];
    __shared__ int   si[256];
    sv[t] = bv; si[t] = bi;
    __syncthreads();
    for (int s = 128; s > 0; s >>= 1) {
        if (t < s) {
            float ov = sv[t + s]; int oi = si[t + s];
            if (ov > sv[t] || (ov == sv[t] && oi < si[t])) { sv[t] = ov; si[t] = oi; }
        }
        __syncthreads();
    }
    float m = sv[0];
    if (t == 0) g_cluster[i] = si[0];
    __syncthreads();

    float e0 = expf(v0 - m), e1 = expf(v1 - m);
    sv[t] = e0 + e1;
    __syncthreads();
    for (int s = 128; s > 0; s >>= 1) {
        if (t < s) sv[t] += sv[t + s];
        __syncthreads();
    }
    float invsum = 1.0f / sv[0];
    S[(size_t)i * CC + t]       = e0 * invsum;
    S[(size_t)i * CC + t + 256] = e1 * invsum;
}

// ---------------- score layer -------------------------------------------------
__global__ void k_hs(const float* __restrict__ x, const float* __restrict__ Ws) {
    int g = blockIdx.x * blockDim.x + threadIdx.x;
    int w = g >> 5, lane = g & 31;
    if (w >= NN) return;
    float s = 0.f;
    for (int f = lane; f < FF; f += 32) s = fmaf(x[(size_t)w * FF + f], Ws[f], s);
#pragma unroll
    for (int off = 16; off > 0; off >>= 1) s += __shfl_down_sync(0xFFFFFFFF, s, off);
    if (lane == 0) g_hs[w] = s;
}

__global__ void k_intradeg(const int* __restrict__ ei) {
    int e = blockIdx.x * blockDim.x + threadIdx.x;
    if (e >= EE) return;
    int s = ei[e], d = ei[EE + e];
    int cs = g_cluster[s], cd = g_cluster[d];
    if (cs == cd) {
        atomicAdd(&g_sdeg[d], 1);
        atomicAdd(&g_icnt[cs], 1);
    }
}

__global__ void k_invs() {
    int i = blockIdx.x * blockDim.x + threadIdx.x;
    if (i < NN) g_invs[i] = rsqrtf((float)g_sdeg[i] + 1.0f);
}

__global__ void k_sagg(const int* __restrict__ ei) {
    int e = blockIdx.x * blockDim.x + threadIdx.x;
    if (e >= EE) return;
    int s = ei[e], d = ei[EE + e];
    if (g_cluster[s] == g_cluster[d])
        atomicAdd(&g_sagg[d], g_invs[s] * g_invs[d] * g_hs[s]);
}

__global__ void k_score(const float* __restrict__ bs) {
    int i = blockIdx.x * blockDim.x + threadIdx.x;
    if (i >= NN) return;
    float inv = g_invs[i];
    float v = g_sagg[i] + inv * inv * g_hs[i] + bs[0];
    g_score[i] = tanhf(v);
}

__global__ void k_segmax() {
    int i = blockIdx.x * blockDim.x + threadIdx.x;
    if (i >= NN) return;
    atomicMax(&g_segkey[g_cluster[i]], fkey(g_score[i]));
}

__global__ void k_segidx() {
    int i = blockIdx.x * blockDim.x + threadIdx.x;
    if (i >= NN) return;
    int c = g_cluster[i];
    float mx = fdec(g_segkey[c]);
    if (g_score[i] >= mx) atomicMin(&g_segidx[c], i);
}

// ---------------- pooling + adjacency ----------------------------------------
__global__ void __launch_bounds__(128) k_pool(const float* __restrict__ x,
                                              float* __restrict__ out) {
    int c = blockIdx.x;
    bool ne = g_icnt[c] > 0;
    float alpha = ne ? fdec(g_segkey[c]) : 0.f;
    int idx = min(g_segidx[c], NN - 1);
    out[(size_t)c * FF + threadIdx.x] = x[(size_t)idx * FF + threadIdx.x] * alpha;
}

__global__ void k_adj(const int* __restrict__ ei, float* __restrict__ out) {
    int e = blockIdx.x * blockDim.x + threadIdx.x;
    if (e >= EE) return;
    int cs = g_cluster[ei[e]], cd = g_cluster[ei[EE + e]];
    if (cs != cd && g_icnt[cs] > 0 && g_icnt[cd] > 0)
        out[OFF_ADJ + (size_t)cs * CC + cd] = 1.0f;
}

// ---------------- launch ------------------------------------------------------
extern "C" void kernel_launch(void* const* d_in, const int* in_sizes, int n_in,
                              void* d_out, int out_size) {
    const float* x   = (const float*)d_in[0];
    const int*   ei  = (const int*)d_in[1];
    const float* W1  = (const float*)d_in[3];
    const float* b1  = (const float*)d_in[4];
    const float* W2  = (const float*)d_in[5];
    const float* b2  = (const float*)d_in[6];
    const float* W3  = (const float*)d_in[7];
    const float* b3  = (const float*)d_in[8];
    const float* Ws  = (const float*)d_in[9];
    const float* bs  = (const float*)d_in[10];
    float* out = (float*)d_out;

    const int EB = (EE + 255) / 256;
    const int NB = (NN + 255) / 256;

    k_init<<<512, 256>>>(out);
    k_deg<<<EB, 256>>>(ei);
    k_inv<<<NB, 256>>>();
    k_scan1<<<NB, 256>>>();
    k_scan2<<<1, 256>>>(NB);
    k_scan3<<<NB, 256>>>();
    k_fill<<<EB, 256>>>(ei);

    // layer 1: z = Ahat @ x (128); h = relu(z @ W1 + b1) (256)
    k_agg<128><<<NN, 128>>>(x, g_z);
    {
        dim3 g(HH / 128, (NN + 127) / 128);
        k_gemm<<<g, 256>>>(g_z, W1, b1, g_h, NN, FF, HH);
    }
    // layer 2: z = Ahat @ h (256); h = relu(z @ W2 + b2) (256)
    k_agg<256><<<NN, 256>>>(g_h, g_z);
    {
        dim3 g(HH / 128, (NN + 127) / 128);
        k_gemm<<<g, 256>>>(g_z, W2, b2, g_h, NN, HH, HH);
    }
    // layer 3: z = Ahat @ h (256); logits = relu(z @ W3 + b3) (512)
    k_agg<256><<<NN, 256>>>(g_h, g_z);
    {
        dim3 g(CC / 128, (NN + 127) / 128);
        k_gemm<<<g, 256>>>(g_z, W3, b3, g_h, NN, HH, CC);
    }

    k_softmax<<<NN, 256>>>(g_h, out + OFF_S);

    k_hs<<<(NN * 32 + 255) / 256, 256>>>(x, Ws);
    k_intradeg<<<EB, 256>>>(ei);
    k_invs<<<NB, 256>>>();
    k_sagg<<<EB, 256>>>(ei);
    k_score<<<NB, 256>>>(bs);
    k_segmax<<<NB, 256>>>();
    k_segidx<<<NB, 256>>>();
    k_pool<<<CC, 128>>>(x, out);
    k_adj<<<EB, 256>>>(ei, out);

    (void)in_sizes; (void)n_in; (void)out_size;
}